// round 1
// baseline (speedup 1.0000x reference)
#include <cuda_runtime.h>

// PrimaryCaps: 3x GEMM [16384,768]x[768,512] + bias + squash(groups of 8)
// Output col n = r*8 + c maps contiguously: out[b, m*512 + n], row stride 1536.
//
// Tile: BM=128 x BN=256, BK=16. 512 threads, 8x8 microtile.
// tx = tid%32 covers cols [n0+tx*8, n0+tx*8+8)  (= one full squash group per row)
// ty = tid/32 covers rows [b0+ty*8, b0+ty*8+8)

#define BM 128
#define BN 256
#define BK 16

#define BATCH 16384
#define IN_CH 768
#define OUT_ROW 1536   // 3*512 floats per batch row

__global__ __launch_bounds__(512, 1)
void primarycaps_kernel(const float* __restrict__ x_img,
                        const float* __restrict__ x_capt,
                        const float* __restrict__ x_dct,
                        const float* __restrict__ w_img,
                        const float* __restrict__ b_img,
                        const float* __restrict__ w_capt,
                        const float* __restrict__ b_capt,
                        const float* __restrict__ w_dct,
                        const float* __restrict__ b_dct,
                        float* __restrict__ out)
{
    __shared__ float As[BK][BM + 4];   // +4 pad keeps 16B align, shifts banks
    __shared__ float Bs[BK][BN + 4];

    const int tid = threadIdx.x;
    const int tx  = tid & 31;          // N dim: 32 groups of 8 cols
    const int ty  = tid >> 5;          // M dim: 16 groups of 8 rows

    const int b0 = blockIdx.x * BM;    // batch tile
    const int n0 = blockIdx.y * BN;    // column tile (0 or 256)
    const int m  = blockIdx.z;         // modality

    const float* X;  const float* W;  const float* Bv;
    if (m == 0)      { X = x_img;  W = w_img;  Bv = b_img;  }
    else if (m == 1) { X = x_capt; W = w_capt; Bv = b_capt; }
    else             { X = x_dct;  W = w_dct;  Bv = b_dct;  }

    // ---- precompute global load coordinates ----
    // A: each thread loads one float4: row = tid/4, kq = tid%4
    const int a_row = tid >> 2;
    const int a_kq  = (tid & 3) * 4;
    const float* a_gptr = X + (size_t)(b0 + a_row) * IN_CH + a_kq;

    // B: each thread loads two float4: idx = q*512 + tid; n_local = idx/4, kq = idx%4
    // weight row for output col n: ((n&7)*64 + (n>>3)) * 768
    int   b_nl[2], b_kq[2];
    const float* b_gptr[2];
    #pragma unroll
    for (int q = 0; q < 2; ++q) {
        int idx  = q * 512 + tid;
        b_nl[q]  = idx >> 2;
        b_kq[q]  = (idx & 3) * 4;
        int n    = n0 + b_nl[q];
        int wrow = ((n & 7) << 6) + (n >> 3);
        b_gptr[q] = W + (size_t)wrow * IN_CH + b_kq[q];
    }

    float acc[8][8];
    #pragma unroll
    for (int i = 0; i < 8; ++i)
        #pragma unroll
        for (int j = 0; j < 8; ++j)
            acc[i][j] = 0.0f;

    for (int k0 = 0; k0 < IN_CH; k0 += BK) {
        // ---- global -> shared ----
        {
            float4 av = *(const float4*)(a_gptr + k0);
            As[a_kq + 0][a_row] = av.x;
            As[a_kq + 1][a_row] = av.y;
            As[a_kq + 2][a_row] = av.z;
            As[a_kq + 3][a_row] = av.w;
            #pragma unroll
            for (int q = 0; q < 2; ++q) {
                float4 bv = *(const float4*)(b_gptr[q] + k0);
                Bs[b_kq[q] + 0][b_nl[q]] = bv.x;
                Bs[b_kq[q] + 1][b_nl[q]] = bv.y;
                Bs[b_kq[q] + 2][b_nl[q]] = bv.z;
                Bs[b_kq[q] + 3][b_nl[q]] = bv.w;
            }
        }
        __syncthreads();

        // ---- compute ----
        #pragma unroll 4
        for (int k = 0; k < BK; ++k) {
            float4 a0 = *(const float4*)&As[k][ty * 8];
            float4 a1 = *(const float4*)&As[k][ty * 8 + 4];
            float4 c0 = *(const float4*)&Bs[k][tx * 8];
            float4 c1 = *(const float4*)&Bs[k][tx * 8 + 4];
            float a[8] = {a0.x, a0.y, a0.z, a0.w, a1.x, a1.y, a1.z, a1.w};
            float b[8] = {c0.x, c0.y, c0.z, c0.w, c1.x, c1.y, c1.z, c1.w};
            #pragma unroll
            for (int i = 0; i < 8; ++i)
                #pragma unroll
                for (int j = 0; j < 8; ++j)
                    acc[i][j] = fmaf(a[i], b[j], acc[i][j]);
        }
        __syncthreads();
    }

    // ---- epilogue: bias + squash over the 8 cols each thread owns ----
    // col n = n0 + tx*8 + j -> c = j, r = n0/8 + tx
    const int gr = (n0 >> 3) + tx;
    float bias[8];
    #pragma unroll
    for (int j = 0; j < 8; ++j)
        bias[j] = Bv[j * 64 + gr];

    float* orow = out + (size_t)(b0 + ty * 8) * OUT_ROW + m * 512 + n0 + tx * 8;

    #pragma unroll
    for (int i = 0; i < 8; ++i) {
        float u[8];
        float sq = 0.0f;
        #pragma unroll
        for (int j = 0; j < 8; ++j) {
            u[j] = acc[i][j] + bias[j];
            sq = fmaf(u[j], u[j], sq);
        }
        float scale = sq / ((1.0f + sq) * sqrtf(sq + 1e-7f));
        float4 o0 = make_float4(u[0]*scale, u[1]*scale, u[2]*scale, u[3]*scale);
        float4 o1 = make_float4(u[4]*scale, u[5]*scale, u[6]*scale, u[7]*scale);
        *(float4*)(orow + (size_t)i * OUT_ROW)     = o0;
        *(float4*)(orow + (size_t)i * OUT_ROW + 4) = o1;
    }
}

extern "C" void kernel_launch(void* const* d_in, const int* in_sizes, int n_in,
                              void* d_out, int out_size)
{
    const float* x_img  = (const float*)d_in[0];
    const float* x_capt = (const float*)d_in[1];
    const float* x_dct  = (const float*)d_in[2];
    const float* w_img  = (const float*)d_in[3];
    const float* b_img  = (const float*)d_in[4];
    const float* w_capt = (const float*)d_in[5];
    const float* b_capt = (const float*)d_in[6];
    const float* w_dct  = (const float*)d_in[7];
    const float* b_dct  = (const float*)d_in[8];
    float* out = (float*)d_out;

    dim3 grid(BATCH / BM, 512 / BN, 3);   // (128, 2, 3)
    dim3 block(512);
    primarycaps_kernel<<<grid, block>>>(x_img, x_capt, x_dct,
                                        w_img, b_img, w_capt, b_capt, w_dct, b_dct,
                                        out);
}